// round 7
// baseline (speedup 1.0000x reference)
#include <cuda_runtime.h>
#include <math.h>

#define N_ROWS 48000
#define DIMS   256
#define KCODES 1024
#define GK     64

#define BM 64          // rows per CTA
#define BN 64          // codes per tile
#define DC 32          // d-chunk for cb staging (double-buffered)
#define XP 66          // xs pitch (words) for transposed [d][row] tile; even -> LDS.64 aligned
#define CBW (DC*BN)    // words per cb chunk buffer
#define DECAYF 0.99f
#define OMDF   0.01f
#define EPSF   1e-5f

typedef unsigned long long ull;

// ---------------- scratch (no allocation allowed) ----------------
__device__ float g_shape_sum[KCODES * DIMS];
__device__ float g_shape_cnt[KCODES];
__device__ float g_gain_sum[GK];
__device__ float g_gain_cnt[GK];

__global__ void init_kernel() {
    int i = blockIdx.x * blockDim.x + threadIdx.x;
    if (i < KCODES * DIMS) g_shape_sum[i] = 0.f;
    if (i < KCODES)        g_shape_cnt[i] = 0.f;
    if (i < GK)  { g_gain_sum[i] = 0.f; g_gain_cnt[i] = 0.f; }
}

// ---------------- packed fp32x2 helpers ----------------
__device__ __forceinline__ ull pack2(float a, float b) {
    ull r; asm("mov.b64 %0, {%1,%2};" : "=l"(r) : "f"(a), "f"(b)); return r;
}
__device__ __forceinline__ void unpack2(ull v, float& lo, float& hi) {
    asm("mov.b64 {%0,%1}, %2;" : "=f"(lo), "=f"(hi) : "l"(v));
}
__device__ __forceinline__ void ffma2(ull& d, ull a, ull b) {
    asm("fma.rn.f32x2 %0, %1, %2, %0;" : "+l"(d) : "l"(a), "l"(b));
}

// stage one 32d x 64c cb chunk, transposed to [dl][c], into buf (conflict-free)
__device__ __forceinline__ void stage_cb(const float* __restrict__ cb,
                                         float* __restrict__ dst,
                                         int q, int tid) {
    int c  = tid & 63;
    int dg = tid >> 6;                   // 0..3
    int ct = q >> 3;                     // code tile
    int dcc = q & 7;                     // d chunk within dims
    const float* src = cb + (size_t)(ct * BN + c) * DIMS + dcc * DC;
    #pragma unroll
    for (int w = 0; w < 2; w++) {
        int dloc = dg * 8 + w * 4;
        float4 v = *(const float4*)(src + dloc);
        dst[(dloc + 0) * BN + c] = v.x;
        dst[(dloc + 1) * BN + c] = v.y;
        dst[(dloc + 2) * BN + c] = v.z;
        dst[(dloc + 3) * BN + c] = v.w;
    }
}

// ---------------- main: GEMM(f32x2) + argmax + gain quant + scatter ----------
__global__ __launch_bounds__(256) void vq_main(
    const float* __restrict__ x,
    const float* __restrict__ cb,
    const float* __restrict__ gcb,
    float* __restrict__ out_q)
{
    extern __shared__ float sm[];
    float* xs    = sm;                      // [256][XP]  transposed: xs[d*XP + r]
    float* cbs   = xs + DIMS * XP;          // 2 x [DC][BN]
    float* gains = cbs + 2 * CBW;           // [64]
    float* bval  = gains + GK;              // [64]
    int*   bidx  = (int*)(bval + BM);       // [64]
    float* bscale= (float*)(bidx + BM);     // [64]

    const int tid = threadIdx.x;
    const int row0 = blockIdx.x * BM;
    const int tx = tid & 15;      // code group 0..15 (4 codes each)
    const int ty = tid >> 4;      // row group 0..15 (4 rows each)

    // ---- stage x tile TRANSPOSED: xs[d][r] ----
    {
        int r = tid & 63;                // row
        int g = tid >> 6;                // 0..3 d-quarter
        #pragma unroll
        for (int p = 0; p < 16; p++) {
            int d4 = g * 64 + p * 4;
            float4 v = *(const float4*)(x + (size_t)(row0 + r) * DIMS + d4);
            xs[(d4 + 0) * XP + r] = v.x;
            xs[(d4 + 1) * XP + r] = v.y;
            xs[(d4 + 2) * XP + r] = v.z;
            xs[(d4 + 3) * XP + r] = v.w;
        }
    }
    if (tid < GK) gains[tid] = gcb[tid];

    // stage first cb chunk
    stage_cb(cb, cbs, 0, tid);
    __syncthreads();

    ull acc[4][2];   // [code j][row pair p]: p=0 -> rows (0,1), p=1 -> rows (2,3)
    #pragma unroll
    for (int j = 0; j < 4; j++) { acc[j][0] = 0ULL; acc[j][1] = 0ULL; }

    float runv[4]; int runi[4];
    #pragma unroll
    for (int i = 0; i < 4; i++) { runv[i] = -3.4e38f; runi[i] = 0; }

    const int NCHUNK = (KCODES / BN) * (DIMS / DC);   // 128
    for (int q = 0; q < NCHUNK; q++) {
        if (q + 1 < NCHUNK)
            stage_cb(cb, cbs + ((q + 1) & 1) * CBW, q + 1, tid);

        const float* cbuf = cbs + (q & 1) * CBW;
        const int dbase = (q & 7) * DC;
        const float* xbase = xs + dbase * XP + ty * 4;

        #pragma unroll 4
        for (int dl = 0; dl < DC; dl++) {
            ull xp0 = *(const ull*)(xbase + dl * XP);       // rows r0, r0+1
            ull xp1 = *(const ull*)(xbase + dl * XP + 2);   // rows r0+2, r0+3
            float4 cv = *(const float4*)(cbuf + dl * BN + (tx << 2));
            ull c0 = pack2(cv.x, cv.x);
            ull c1 = pack2(cv.y, cv.y);
            ull c2 = pack2(cv.z, cv.z);
            ull c3 = pack2(cv.w, cv.w);
            ffma2(acc[0][0], xp0, c0); ffma2(acc[0][1], xp1, c0);
            ffma2(acc[1][0], xp0, c1); ffma2(acc[1][1], xp1, c1);
            ffma2(acc[2][0], xp0, c2); ffma2(acc[2][1], xp1, c2);
            ffma2(acc[3][0], xp0, c3); ffma2(acc[3][1], xp1, c3);
        }

        if ((q & 7) == 7) {
            // tile done: unpack accumulators -> av[row i][code j]
            int ct = q >> 3;
            float av[4][4];
            #pragma unroll
            for (int j = 0; j < 4; j++) {
                unpack2(acc[j][0], av[0][j], av[1][j]);
                unpack2(acc[j][1], av[2][j], av[3][j]);
                acc[j][0] = 0ULL; acc[j][1] = 0ULL;
            }
            #pragma unroll
            for (int i = 0; i < 4; i++) {
                float bv = av[i][0]; int bj = 0;
                if (av[i][1] > bv) { bv = av[i][1]; bj = 1; }
                if (av[i][2] > bv) { bv = av[i][2]; bj = 2; }
                if (av[i][3] > bv) { bv = av[i][3]; bj = 3; }
                int bc = ct * BN + tx * 4 + bj;
                #pragma unroll
                for (int off = 1; off < 16; off <<= 1) {
                    float ov = __shfl_xor_sync(0xffffffffu, bv, off);
                    int   oc = __shfl_xor_sync(0xffffffffu, bc, off);
                    if (ov > bv || (ov == bv && oc < bc)) { bv = ov; bc = oc; }
                }
                if (bv > runv[i]) { runv[i] = bv; runi[i] = bc; }
            }
        }
        __syncthreads();
    }

    if (tx == 0) {
        #pragma unroll
        for (int i = 0; i < 4; i++) {
            bval[ty * 4 + i] = runv[i];
            bidx[ty * 4 + i] = runi[i];
        }
    }
    __syncthreads();

    // ---- gain quantization + scalar stats (one thread per row) ----
    if (tid < BM) {
        float g = logf(fmaxf(bval[tid], EPSF));   // LOG_GAIN, clip min EPS
        float bd = 3.4e38f; int gi = 0;
        #pragma unroll
        for (int j = 0; j < GK; j++) {
            float d = g - gains[j];
            float d2 = d * d;
            if (d2 < bd) { bd = d2; gi = j; }     // first-min == first argmax of -d2
        }
        atomicAdd(&g_gain_sum[gi], g);
        atomicAdd(&g_gain_cnt[gi], 1.f);
        atomicAdd(&g_shape_cnt[bidx[tid]], 1.f);
        bscale[tid] = expf(gains[gi]);            // exp(gain_q)
    }
    __syncthreads();

    // ---- epilogue: quantize output + shape_sum scatter ----
    for (int r = 0; r < BM; r++) {
        int k = bidx[r];
        float sc = bscale[r];
        float cv = cb[(size_t)k * DIMS + tid];
        out_q[(size_t)(row0 + r) * DIMS + tid] = sc * cv;
        atomicAdd(&g_shape_sum[(size_t)k * DIMS + tid],
                  x[(size_t)(row0 + r) * DIMS + tid]);
    }
}

// ---------------- finalize: EMA updates ----------------
__device__ __forceinline__ float blockSum256(float v, float* red) {
    __syncthreads();
    int lane = threadIdx.x & 31, w = threadIdx.x >> 5;
    #pragma unroll
    for (int o = 16; o; o >>= 1) v += __shfl_xor_sync(0xffffffffu, v, o);
    if (lane == 0) red[w] = v;
    __syncthreads();
    if (w == 0) {
        float t = (lane < 8) ? red[lane] : 0.f;
        #pragma unroll
        for (int o = 4; o; o >>= 1) t += __shfl_xor_sync(0xffffffffu, t, o);
        if (lane == 0) red[0] = t;
    }
    __syncthreads();
    return red[0];
}

__global__ __launch_bounds__(256) void vq_finalize(
    const float* __restrict__ cb,   const float* __restrict__ gcb,
    const float* __restrict__ snum, const float* __restrict__ gnum,
    float* __restrict__ out_shape,  float* __restrict__ out_gain,
    float* __restrict__ out_snum,   float* __restrict__ out_gnum)
{
    __shared__ float red[8];
    int k = blockIdx.x, t = threadIdx.x;

    float s = g_shape_sum[k * DIMS + t];
    float ss = blockSum256(s * s, red);
    float denom = fmaxf(sqrtf(ss), EPSF);             // clip(norm, EPS)
    float upd = cb[k * DIMS + t] * DECAYF + (s / denom) * OMDF;
    float nn = blockSum256(upd * upd, red);
    float n2 = fmaxf(sqrtf(nn), 1e-12f);              // _l2norm clip 1e-12
    out_shape[k * DIMS + t] = upd / n2;

    if (t == 0)
        out_snum[k] = snum[k] * DECAYF + g_shape_cnt[k] * OMDF;

    if (k == 0 && t < GK) {
        float cnt  = g_gain_cnt[t];
        float gnew = g_gain_sum[t] / fmaxf(cnt, EPSF);
        out_gain[t] = gcb[t]  * DECAYF + gnew * OMDF;
        out_gnum[t] = gnum[t] * DECAYF + cnt  * OMDF;
    }
}

// ---------------- launch ----------------
extern "C" void kernel_launch(void* const* d_in, const int* in_sizes, int n_in,
                              void* d_out, int out_size) {
    const float* x    = (const float*)d_in[0];   // (48000, 256)
    const float* cb   = (const float*)d_in[1];   // (1024, 256)
    const float* gcb  = (const float*)d_in[2];   // (64,)
    const float* snum = (const float*)d_in[3];   // (1024,)
    const float* gnum = (const float*)d_in[4];   // (64,)

    float* out       = (float*)d_out;
    float* out_q     = out;                             // 12,288,000
    float* out_shape = out_q + (size_t)N_ROWS * DIMS;   // 262,144
    float* out_gain  = out_shape + KCODES * DIMS;       // 64
    float* out_snum  = out_gain + GK;                   // 1024
    float* out_gnum  = out_snum + KCODES;               // 64

    init_kernel<<<(KCODES * DIMS + 255) / 256, 256>>>();

    size_t smem = (size_t)(DIMS * XP + 2 * CBW + GK + BM + BM + BM) * 4;
    cudaFuncSetAttribute(vq_main, cudaFuncAttributeMaxDynamicSharedMemorySize,
                         (int)smem);
    vq_main<<<N_ROWS / BM, 256, smem>>>(x, cb, gcb, out_q);

    vq_finalize<<<KCODES, 256>>>(cb, gcb, snum, gnum,
                                 out_shape, out_gain, out_snum, out_gnum);
}

// round 8
// speedup vs baseline: 2.5882x; 2.5882x over previous
#include <cuda_runtime.h>
#include <math.h>

#define N_ROWS 48000
#define DIMS   256
#define KCODES 1024
#define GK     64
#define NB     (N_ROWS / 64)        // 750 row-blocks
#define CI_N   8                    // col iterations (128 cols each)
#define KC_N   4                    // k chunks (64 k each = 8 ksteps)
#define DELTA  1.0f                 // rescore margin (>>50 sigma of tf32 noise)
#define DECAYF 0.99f
#define OMDF   0.01f
#define EPSF   1e-5f

// ---------------- scratch (static device globals; no runtime alloc) --------
__device__ float4 g_xfrag[NB * 4 * 32 * 32];      // [blk][wr][ks][lane] 49 MB
__device__ float2 g_bfrag[CI_N * 2 * 8 * 32 * 32]; // [ci][wc][st][ks][lane] 1 MB
__device__ float  g_shape_sum[KCODES * DIMS];
__device__ float  g_shape_cnt[KCODES];
__device__ float  g_gain_sum[GK];
__device__ float  g_gain_cnt[GK];

__global__ void init_kernel() {
    int i = blockIdx.x * blockDim.x + threadIdx.x;
    if (i < KCODES * DIMS) g_shape_sum[i] = 0.f;
    if (i < KCODES)        g_shape_cnt[i] = 0.f;
    if (i < GK)  { g_gain_sum[i] = 0.f; g_gain_cnt[i] = 0.f; }
}

// ---------------- tf32 helpers ----------------
__device__ __forceinline__ float to_tf32(float f) {
    unsigned u;
    asm("cvt.rna.tf32.f32 %0, %1;" : "=r"(u) : "f"(f));
    return __uint_as_float(u);
}

__device__ __forceinline__ void mma_tf32(float c[4], float4 a, float2 b) {
    asm volatile(
        "mma.sync.aligned.m16n8k8.row.col.f32.tf32.tf32.f32 "
        "{%0,%1,%2,%3},{%4,%5,%6,%7},{%8,%9},{%0,%1,%2,%3};"
        : "+f"(c[0]), "+f"(c[1]), "+f"(c[2]), "+f"(c[3])
        : "r"(__float_as_uint(a.x)), "r"(__float_as_uint(a.y)),
          "r"(__float_as_uint(a.z)), "r"(__float_as_uint(a.w)),
          "r"(__float_as_uint(b.x)), "r"(__float_as_uint(b.y)));
}

// ---------------- prep: x -> A-fragment layout (tf32) ----------------
// g_xfrag[blk][wr][ks][lane] = (x[r][k], x[r+8][k], x[r][k+4], x[r+8][k+4])
//   r = blk*64 + wr*16 + (lane>>2), k = ks*8 + (lane&3)
__global__ __launch_bounds__(256) void prep_x(const float* __restrict__ x) {
    int blk = blockIdx.x, tid = threadIdx.x;
    int wr = tid >> 6, lane = tid & 31, half = (tid >> 5) & 1;
    int r0 = blk * 64 + wr * 16 + (lane >> 2);
    #pragma unroll
    for (int s = 0; s < 16; s++) {
        int ks = half * 16 + s;
        int k = ks * 8 + (lane & 3);
        float4 v;
        v.x = to_tf32(x[(size_t)r0 * DIMS + k]);
        v.y = to_tf32(x[(size_t)(r0 + 8) * DIMS + k]);
        v.z = to_tf32(x[(size_t)r0 * DIMS + k + 4]);
        v.w = to_tf32(x[(size_t)(r0 + 8) * DIMS + k + 4]);
        g_xfrag[blk * 4096 + wr * 1024 + ks * 32 + lane] = v;
    }
}

// ---------------- prep: cb -> B-fragment layout (tf32) ----------------
// col = ci*128 + wc*64 + st*8 + (lane>>2), k = ks*8 + (lane&3)
__global__ __launch_bounds__(256) void prep_cb(const float* __restrict__ cb) {
    int i = blockIdx.x * 256 + threadIdx.x;   // 131072 total
    int lane = i & 31, ks = (i >> 5) & 31, st = (i >> 10) & 7;
    int wc = (i >> 13) & 1, ci = i >> 14;
    int col = ci * 128 + wc * 64 + st * 8 + (lane >> 2);
    int k = ks * 8 + (lane & 3);
    float2 v;
    v.x = to_tf32(cb[(size_t)col * DIMS + k]);
    v.y = to_tf32(cb[(size_t)col * DIMS + k + 4]);
    g_bfrag[i] = v;
}

// ---------------- top-3 insert ----------------
__device__ __forceinline__ void ins3(float* tv, int* tix, float v, int j) {
    if (v > tv[0])      { tv[2]=tv[1]; tix[2]=tix[1]; tv[1]=tv[0]; tix[1]=tix[0]; tv[0]=v; tix[0]=j; }
    else if (v > tv[1]) { tv[2]=tv[1]; tix[2]=tix[1]; tv[1]=v; tix[1]=j; }
    else if (v > tv[2]) { tv[2]=v; tix[2]=j; }
}

// ---------------- main: tf32 MMA coarse + exact rescore + epilogue --------
__global__ __launch_bounds__(256) void vq_main(
    const float* __restrict__ x,
    const float* __restrict__ cb,
    const float* __restrict__ gcb,
    float* __restrict__ out_q)
{
    extern __shared__ float sm[];
    float4* sxf = (float4*)sm;               // 4096 float4 (64 KB) A frags
    float2* sbf = (float2*)(sm + 16384);     // 4096 float2 (32 KB) B frags
    float*  cvv = sm + 24576;                // 1536 candidate values
    int*    cix = (int*)(cvv + 1536);        // 1536 candidate indices
    float*  gains = (float*)(cix + 1536);    // 64
    float*  bval  = gains + GK;              // 64
    int*    bidx  = (int*)(bval + 64);       // 64
    float*  bscale= (float*)(bidx + 64);     // 64

    const int tid = threadIdx.x, blk = blockIdx.x;
    const int lane = tid & 31, wid = tid >> 5;
    const int wr = wid & 3, wc = wid >> 2;
    const int row0 = blk * 64;

    // stage A fragments (64 KB, coalesced)
    #pragma unroll
    for (int i = 0; i < 16; i++)
        sxf[tid + i * 256] = g_xfrag[blk * 4096 + tid + i * 256];
    if (tid < GK) gains[tid] = gcb[tid];

    float tv0[3], tv1[3]; int tx0[3], tx1[3];
    #pragma unroll
    for (int e = 0; e < 3; e++) { tv0[e] = -3.4e38f; tv1[e] = -3.4e38f; tx0[e] = 0; tx1[e] = 0; }

    const float4* gb4 = (const float4*)g_bfrag;

    for (int ci = 0; ci < CI_N; ci++) {
        float acc[8][4];
        #pragma unroll
        for (int st = 0; st < 8; st++)
            #pragma unroll
            for (int q = 0; q < 4; q++) acc[st][q] = 0.f;

        for (int kc = 0; kc < KC_N; kc++) {
            __syncthreads();
            // stage B fragments for (ci, kc): 2048 float4, 8 per thread
            #pragma unroll
            for (int i = 0; i < 8; i++) {
                int f = tid + i * 256;
                int slice = f >> 7, w = f & 127;
                ((float4*)sbf)[f] = gb4[(ci * 16 + slice) * 512 + kc * 128 + w];
            }
            __syncthreads();

            #pragma unroll
            for (int ksp = 0; ksp < 8; ksp++) {
                float4 A = sxf[wr * 1024 + (kc * 8 + ksp) * 32 + lane];
                #pragma unroll
                for (int st = 0; st < 8; st++) {
                    float2 B = sbf[((wc * 8 + st) * 8 + ksp) * 32 + lane];
                    mma_tf32(acc[st], A, B);
                }
            }
        }

        // coarse top-3 update (2 row-slots per thread)
        #pragma unroll
        for (int st = 0; st < 8; st++) {
            int cb0 = ci * 128 + wc * 64 + st * 8 + 2 * (lane & 3);
            ins3(tv0, tx0, acc[st][0], cb0);
            ins3(tv0, tx0, acc[st][1], cb0 + 1);
            ins3(tv1, tx1, acc[st][2], cb0);
            ins3(tv1, tx1, acc[st][3], cb0 + 1);
        }
    }

    // merge candidates to smem: 8 slots x 3 entries per row
    {
        int rA = wr * 16 + (lane >> 2), rB = rA + 8;
        int slot = wc * 4 + (lane & 3);
        #pragma unroll
        for (int e = 0; e < 3; e++) {
            cvv[rA * 24 + slot * 3 + e] = tv0[e];
            cix[rA * 24 + slot * 3 + e] = tx0[e];
            cvv[rB * 24 + slot * 3 + e] = tv1[e];
            cix[rB * 24 + slot * 3 + e] = tx1[e];
        }
    }
    __syncthreads();

    // ---- exact fp32 rescore of in-margin candidates (one thread per row) ----
    if (tid < 64) {
        int row = tid;
        float m = -3.4e38f;
        #pragma unroll 4
        for (int e = 0; e < 24; e++) m = fmaxf(m, cvv[row * 24 + e]);

        float best = -3.4e38f; int bj = 0x7fffffff;
        const float4* xr = (const float4*)(x + (size_t)(row0 + row) * DIMS);
        for (int e = 0; e < 24; e++) {
            float c = cvv[row * 24 + e];
            if (c >= m - DELTA) {
                int j = cix[row * 24 + e];
                const float4* cr = (const float4*)(cb + (size_t)j * DIMS);
                float a0 = 0.f, a1 = 0.f, a2 = 0.f, a3 = 0.f;
                #pragma unroll 8
                for (int i = 0; i < 64; i++) {
                    float4 xv = xr[i], cw = cr[i];
                    a0 = fmaf(xv.x, cw.x, a0);
                    a1 = fmaf(xv.y, cw.y, a1);
                    a2 = fmaf(xv.z, cw.z, a2);
                    a3 = fmaf(xv.w, cw.w, a3);
                }
                float ex = (a0 + a1) + (a2 + a3);
                if (ex > best || (ex == best && j < bj)) { best = ex; bj = j; }
            }
        }
        bval[row] = best; bidx[row] = bj;

        // gain quantization + scalar stats
        float g = logf(fmaxf(best, EPSF));
        float bd = 3.4e38f; int gi = 0;
        #pragma unroll
        for (int q = 0; q < GK; q++) {
            float d = g - gains[q];
            float d2 = d * d;
            if (d2 < bd) { bd = d2; gi = q; }
        }
        atomicAdd(&g_gain_sum[gi], g);
        atomicAdd(&g_gain_cnt[gi], 1.f);
        atomicAdd(&g_shape_cnt[bj], 1.f);
        bscale[row] = expf(gains[gi]);
    }
    __syncthreads();

    // ---- epilogue: quantize output + shape_sum scatter ----
    for (int r = 0; r < 64; r++) {
        int k = bidx[r];
        float sc = bscale[r];
        float cvw = cb[(size_t)k * DIMS + tid];
        out_q[(size_t)(row0 + r) * DIMS + tid] = sc * cvw;
        atomicAdd(&g_shape_sum[(size_t)k * DIMS + tid],
                  x[(size_t)(row0 + r) * DIMS + tid]);
    }
}

// ---------------- finalize: EMA updates ----------------
__device__ __forceinline__ float blockSum256(float v, float* red) {
    __syncthreads();
    int lane = threadIdx.x & 31, w = threadIdx.x >> 5;
    #pragma unroll
    for (int o = 16; o; o >>= 1) v += __shfl_xor_sync(0xffffffffu, v, o);
    if (lane == 0) red[w] = v;
    __syncthreads();
    if (w == 0) {
        float t = (lane < 8) ? red[lane] : 0.f;
        #pragma unroll
        for (int o = 4; o; o >>= 1) t += __shfl_xor_sync(0xffffffffu, t, o);
        if (lane == 0) red[0] = t;
    }
    __syncthreads();
    return red[0];
}

__global__ __launch_bounds__(256) void vq_finalize(
    const float* __restrict__ cb,   const float* __restrict__ gcb,
    const float* __restrict__ snum, const float* __restrict__ gnum,
    float* __restrict__ out_shape,  float* __restrict__ out_gain,
    float* __restrict__ out_snum,   float* __restrict__ out_gnum)
{
    __shared__ float red[8];
    int k = blockIdx.x, t = threadIdx.x;

    float s = g_shape_sum[k * DIMS + t];
    float ss = blockSum256(s * s, red);
    float denom = fmaxf(sqrtf(ss), EPSF);
    float upd = cb[k * DIMS + t] * DECAYF + (s / denom) * OMDF;
    float nn = blockSum256(upd * upd, red);
    float n2 = fmaxf(sqrtf(nn), 1e-12f);
    out_shape[k * DIMS + t] = upd / n2;

    if (t == 0)
        out_snum[k] = snum[k] * DECAYF + g_shape_cnt[k] * OMDF;

    if (k == 0 && t < GK) {
        float cnt  = g_gain_cnt[t];
        float gnew = g_gain_sum[t] / fmaxf(cnt, EPSF);
        out_gain[t] = gcb[t]  * DECAYF + gnew * OMDF;
        out_gnum[t] = gnum[t] * DECAYF + cnt  * OMDF;
    }
}

// ---------------- launch ----------------
extern "C" void kernel_launch(void* const* d_in, const int* in_sizes, int n_in,
                              void* d_out, int out_size) {
    const float* x    = (const float*)d_in[0];   // (48000, 256)
    const float* cb   = (const float*)d_in[1];   // (1024, 256)
    const float* gcb  = (const float*)d_in[2];   // (64,)
    const float* snum = (const float*)d_in[3];   // (1024,)
    const float* gnum = (const float*)d_in[4];   // (64,)

    float* out       = (float*)d_out;
    float* out_q     = out;                             // 12,288,000
    float* out_shape = out_q + (size_t)N_ROWS * DIMS;   // 262,144
    float* out_gain  = out_shape + KCODES * DIMS;       // 64
    float* out_snum  = out_gain + GK;                   // 1024
    float* out_gnum  = out_snum + KCODES;               // 64

    init_kernel<<<(KCODES * DIMS + 255) / 256, 256>>>();
    prep_x<<<NB, 256>>>(x);
    prep_cb<<<512, 256>>>(cb);

    size_t smem = (size_t)(16384 * 4 + 8192 * 4 + 1536 * 4 * 2 + 256 * 4);
    cudaFuncSetAttribute(vq_main, cudaFuncAttributeMaxDynamicSharedMemorySize,
                         (int)smem);
    vq_main<<<NB, 256, smem>>>(x, cb, gcb, out_q);

    vq_finalize<<<KCODES, 256>>>(cb, gcb, snum, gnum,
                                 out_shape, out_gain, out_snum, out_gnum);
}

// round 9
// speedup vs baseline: 3.1154x; 1.2037x over previous
#include <cuda_runtime.h>
#include <math.h>

#define N_ROWS 48000
#define DIMS   256
#define KCODES 1024
#define GK     64
#define NB     (N_ROWS / 64)        // 750 row-blocks
#define CI_N   8                    // col iterations (128 cols each)
#define KC_N   4                    // k chunks (64 k = 4 k16-steps each)
#define DELTA  1.0f                 // rescore margin (~11 sigma of bf16 noise)
#define DECAYF 0.99f
#define OMDF   0.01f
#define EPSF   1e-5f

// ---------------- scratch (static device globals; no runtime alloc) --------
__device__ uint4 g_xfrag[NB * 2048];        // A frags bf16: [blk][wr][ks16][lane] 24.5 MB
__device__ uint2 g_bfrag[128 * 16 * 32];    // B frags bf16: [st][ks16][lane] 512 KB
__device__ float g_shape_sum[KCODES * DIMS];
__device__ float g_shape_cnt[KCODES];
__device__ float g_gain_sum[GK];
__device__ float g_gain_cnt[GK];

__global__ void init_kernel() {
    int i = blockIdx.x * blockDim.x + threadIdx.x;
    if (i < KCODES * DIMS) g_shape_sum[i] = 0.f;
    if (i < KCODES)        g_shape_cnt[i] = 0.f;
    if (i < GK)  { g_gain_sum[i] = 0.f; g_gain_cnt[i] = 0.f; }
}

// ---------------- bf16 helpers ----------------
__device__ __forceinline__ unsigned pk_bf16x2(float lo, float hi) {
    unsigned r;
    asm("cvt.rn.bf16x2.f32 %0, %1, %2;" : "=r"(r) : "f"(hi), "f"(lo));
    return r;
}

__device__ __forceinline__ void mma_bf16(float c[4], uint4 a, uint2 b) {
    asm volatile(
        "mma.sync.aligned.m16n8k16.row.col.f32.bf16.bf16.f32 "
        "{%0,%1,%2,%3},{%4,%5,%6,%7},{%8,%9},{%0,%1,%2,%3};"
        : "+f"(c[0]), "+f"(c[1]), "+f"(c[2]), "+f"(c[3])
        : "r"(a.x), "r"(a.y), "r"(a.z), "r"(a.w), "r"(b.x), "r"(b.y));
}

// ---------------- prep: x -> A-fragment layout (bf16, m16n8k16) ------------
// frag f = wr*512 + ks*32 + lane; r = blk*64 + wr*16 + (lane>>2); k = ks*16 + (lane&3)*2
// a = { (x[r][k],x[r][k+1]), (x[r+8][k],..), (x[r][k+8],..), (x[r+8][k+8],..) }
__global__ __launch_bounds__(256) void prep_x(const float* __restrict__ x) {
    int blk = blockIdx.x, tid = threadIdx.x;
    #pragma unroll
    for (int i = 0; i < 8; i++) {
        int f = tid + i * 256;
        int wr = f >> 9, ks = (f >> 5) & 15, lane = f & 31;
        int r = blk * 64 + wr * 16 + (lane >> 2);
        int k = ks * 16 + (lane & 3) * 2;
        const float* p0 = x + (size_t)r * DIMS + k;
        const float* p1 = x + (size_t)(r + 8) * DIMS + k;
        float2 v00 = *(const float2*)(p0);
        float2 v10 = *(const float2*)(p1);
        float2 v01 = *(const float2*)(p0 + 8);
        float2 v11 = *(const float2*)(p1 + 8);
        uint4 o;
        o.x = pk_bf16x2(v00.x, v00.y);
        o.y = pk_bf16x2(v10.x, v10.y);
        o.z = pk_bf16x2(v01.x, v01.y);
        o.w = pk_bf16x2(v11.x, v11.y);
        g_xfrag[blk * 2048 + f] = o;
    }
}

// ---------------- prep: cb -> B-fragment layout (bf16) ----------------
// i = st*512 + ks*32 + lane; col = st*8 + (lane>>2); k = ks*16 + (lane&3)*2
// b0 = (cb[col][k], cb[col][k+1]); b1 = (cb[col][k+8], cb[col][k+9])
__global__ __launch_bounds__(256) void prep_cb(const float* __restrict__ cb) {
    int i = blockIdx.x * 256 + threadIdx.x;   // 65536
    int lane = i & 31, ks = (i >> 5) & 15, st = i >> 9;
    int col = st * 8 + (lane >> 2);
    int k = ks * 16 + (lane & 3) * 2;
    float2 v0 = *(const float2*)(cb + (size_t)col * DIMS + k);
    float2 v1 = *(const float2*)(cb + (size_t)col * DIMS + k + 8);
    uint2 o;
    o.x = pk_bf16x2(v0.x, v0.y);
    o.y = pk_bf16x2(v1.x, v1.y);
    g_bfrag[i] = o;
}

// ---------------- top-4 insert ----------------
__device__ __forceinline__ void ins4(float* tv, int* tix, float v, int j) {
    if (v > tv[0]) {
        tv[3]=tv[2]; tix[3]=tix[2]; tv[2]=tv[1]; tix[2]=tix[1];
        tv[1]=tv[0]; tix[1]=tix[0]; tv[0]=v; tix[0]=j;
    } else if (v > tv[1]) {
        tv[3]=tv[2]; tix[3]=tix[2]; tv[2]=tv[1]; tix[2]=tix[1];
        tv[1]=v; tix[1]=j;
    } else if (v > tv[2]) {
        tv[3]=tv[2]; tix[3]=tix[2]; tv[2]=v; tix[2]=j;
    } else if (v > tv[3]) {
        tv[3]=v; tix[3]=j;
    }
}

// ---------------- main: bf16 MMA coarse + exact fp32 rescore + epilogue ----
__global__ __launch_bounds__(256, 3) void vq_main(
    const float* __restrict__ x,
    const float* __restrict__ cb,
    const float* __restrict__ gcb,
    float* __restrict__ out_q)
{
    extern __shared__ float sm[];
    uint4* saf  = (uint4*)sm;                 // 2048 uint4 (32 KB) A frags
    uint4* sbf4 = saf + 2048;                 // 1024 uint4 (16 KB) B chunk
    uint2* sbf  = (uint2*)sbf4;
    float* cvv  = (float*)(sbf4 + 1024);      // 2048 candidate values (8 KB)
    int*   cix  = (int*)(cvv + 2048);         // 2048 candidate indices (8 KB)
    float* gains  = (float*)(cix + 2048);     // 64
    float* bval   = gains + GK;               // 64
    int*   bidx   = (int*)(bval + 64);        // 64
    float* bscale = (float*)(bidx + 64);      // 64

    const int tid = threadIdx.x, blk = blockIdx.x;
    const int lane = tid & 31, wid = tid >> 5;
    const int wr = wid & 3, wc = wid >> 2;
    const int row0 = blk * 64;

    // stage A fragments (32 KB, coalesced)
    #pragma unroll
    for (int i = 0; i < 8; i++)
        saf[tid + i * 256] = g_xfrag[blk * 2048 + tid + i * 256];
    if (tid < GK) gains[tid] = gcb[tid];

    float tv0[4], tv1[4]; int tx0[4], tx1[4];
    #pragma unroll
    for (int e = 0; e < 4; e++) {
        tv0[e] = -3.4e38f; tv1[e] = -3.4e38f; tx0[e] = 0; tx1[e] = 0;
    }

    const uint4* gb4 = (const uint4*)g_bfrag;

    for (int ci = 0; ci < CI_N; ci++) {
        float acc[8][4];
        #pragma unroll
        for (int st = 0; st < 8; st++)
            #pragma unroll
            for (int q = 0; q < 4; q++) acc[st][q] = 0.f;

        for (int kc = 0; kc < KC_N; kc++) {
            __syncthreads();
            // stage B frags for (ci, kc): 1024 uint4, 4 per thread
            #pragma unroll
            for (int i = 0; i < 4; i++) {
                int f = tid + i * 256;
                int stl = f >> 6, kspl = (f >> 4) & 3, w = f & 15;
                sbf4[f] = gb4[((ci * 16 + stl) * 16 + kc * 4 + kspl) * 16 + w];
            }
            __syncthreads();

            #pragma unroll
            for (int kspl = 0; kspl < 4; kspl++) {
                uint4 A = saf[wr * 512 + (kc * 4 + kspl) * 32 + lane];
                #pragma unroll
                for (int st = 0; st < 8; st++) {
                    uint2 B = sbf[((wc * 8 + st) * 4 + kspl) * 32 + lane];
                    mma_bf16(acc[st], A, B);
                }
            }
        }

        // coarse top-4 update (2 row-slots per thread)
        #pragma unroll
        for (int st = 0; st < 8; st++) {
            int cb0 = ci * 128 + wc * 64 + st * 8 + 2 * (lane & 3);
            ins4(tv0, tx0, acc[st][0], cb0);
            ins4(tv0, tx0, acc[st][1], cb0 + 1);
            ins4(tv1, tx1, acc[st][2], cb0);
            ins4(tv1, tx1, acc[st][3], cb0 + 1);
        }
    }

    // merge candidates to smem: 8 slots x 4 entries per row
    {
        int rA = wr * 16 + (lane >> 2), rB = rA + 8;
        int slot = wc * 4 + (lane & 3);
        #pragma unroll
        for (int e = 0; e < 4; e++) {
            cvv[rA * 32 + slot * 4 + e] = tv0[e];
            cix[rA * 32 + slot * 4 + e] = tx0[e];
            cvv[rB * 32 + slot * 4 + e] = tv1[e];
            cix[rB * 32 + slot * 4 + e] = tx1[e];
        }
    }
    __syncthreads();

    // ---- exact fp32 rescore of in-margin candidates (one thread per row) ----
    if (tid < 64) {
        int row = tid;
        float m = -3.4e38f;
        #pragma unroll 4
        for (int e = 0; e < 32; e++) m = fmaxf(m, cvv[row * 32 + e]);

        float best = -3.4e38f; int bj = 0x7fffffff;
        const float4* xr = (const float4*)(x + (size_t)(row0 + row) * DIMS);
        for (int e = 0; e < 32; e++) {
            float c = cvv[row * 32 + e];
            if (c >= m - DELTA) {
                int j = cix[row * 32 + e];
                const float4* cr = (const float4*)(cb + (size_t)j * DIMS);
                float a0 = 0.f, a1 = 0.f, a2 = 0.f, a3 = 0.f;
                #pragma unroll 8
                for (int i = 0; i < 64; i++) {
                    float4 xv = xr[i], cw = cr[i];
                    a0 = fmaf(xv.x, cw.x, a0);
                    a1 = fmaf(xv.y, cw.y, a1);
                    a2 = fmaf(xv.z, cw.z, a2);
                    a3 = fmaf(xv.w, cw.w, a3);
                }
                float ex = (a0 + a1) + (a2 + a3);
                if (ex > best || (ex == best && j < bj)) { best = ex; bj = j; }
            }
        }
        bval[row] = best; bidx[row] = bj;

        // gain quantization + scalar stats
        float g = logf(fmaxf(best, EPSF));
        float bd = 3.4e38f; int gi = 0;
        #pragma unroll
        for (int q = 0; q < GK; q++) {
            float d = g - gains[q];
            float d2 = d * d;
            if (d2 < bd) { bd = d2; gi = q; }
        }
        atomicAdd(&g_gain_sum[gi], g);
        atomicAdd(&g_gain_cnt[gi], 1.f);
        atomicAdd(&g_shape_cnt[bj], 1.f);
        bscale[row] = expf(gains[gi]);
    }
    __syncthreads();

    // ---- epilogue: quantize output + shape_sum scatter ----
    for (int r = 0; r < 64; r++) {
        int k = bidx[r];
        float sc = bscale[r];
        float cvw = cb[(size_t)k * DIMS + tid];
        out_q[(size_t)(row0 + r) * DIMS + tid] = sc * cvw;
        atomicAdd(&g_shape_sum[(size_t)k * DIMS + tid],
                  x[(size_t)(row0 + r) * DIMS + tid]);
    }
}

// ---------------- finalize: EMA updates ----------------
__device__ __forceinline__ float blockSum256(float v, float* red) {
    __syncthreads();
    int lane = threadIdx.x & 31, w = threadIdx.x >> 5;
    #pragma unroll
    for (int o = 16; o; o >>= 1) v += __shfl_xor_sync(0xffffffffu, v, o);
    if (lane == 0) red[w] = v;
    __syncthreads();
    if (w == 0) {
        float t = (lane < 8) ? red[lane] : 0.f;
        #pragma unroll
        for (int o = 4; o; o >>= 1) t += __shfl_xor_sync(0xffffffffu, t, o);
        if (lane == 0) red[0] = t;
    }
    __syncthreads();
    return red[0];
}

__global__ __launch_bounds__(256) void vq_finalize(
    const float* __restrict__ cb,   const float* __restrict__ gcb,
    const float* __restrict__ snum, const float* __restrict__ gnum,
    float* __restrict__ out_shape,  float* __restrict__ out_gain,
    float* __restrict__ out_snum,   float* __restrict__ out_gnum)
{
    __shared__ float red[8];
    int k = blockIdx.x, t = threadIdx.x;

    float s = g_shape_sum[k * DIMS + t];
    float ss = blockSum256(s * s, red);
    float denom = fmaxf(sqrtf(ss), EPSF);
    float upd = cb[k * DIMS + t] * DECAYF + (s / denom) * OMDF;
    float nn = blockSum256(upd * upd, red);
    float n2 = fmaxf(sqrtf(nn), 1e-12f);
    out_shape[k * DIMS + t] = upd / n2;

    if (t == 0)
        out_snum[k] = snum[k] * DECAYF + g_shape_cnt[k] * OMDF;

    if (k == 0 && t < GK) {
        float cnt  = g_gain_cnt[t];
        float gnew = g_gain_sum[t] / fmaxf(cnt, EPSF);
        out_gain[t] = gcb[t]  * DECAYF + gnew * OMDF;
        out_gnum[t] = gnum[t] * DECAYF + cnt  * OMDF;
    }
}

// ---------------- launch ----------------
extern "C" void kernel_launch(void* const* d_in, const int* in_sizes, int n_in,
                              void* d_out, int out_size) {
    const float* x    = (const float*)d_in[0];   // (48000, 256)
    const float* cb   = (const float*)d_in[1];   // (1024, 256)
    const float* gcb  = (const float*)d_in[2];   // (64,)
    const float* snum = (const float*)d_in[3];   // (1024,)
    const float* gnum = (const float*)d_in[4];   // (64,)

    float* out       = (float*)d_out;
    float* out_q     = out;                             // 12,288,000
    float* out_shape = out_q + (size_t)N_ROWS * DIMS;   // 262,144
    float* out_gain  = out_shape + KCODES * DIMS;       // 64
    float* out_snum  = out_gain + GK;                   // 1024
    float* out_gnum  = out_snum + KCODES;               // 64

    init_kernel<<<(KCODES * DIMS + 255) / 256, 256>>>();
    prep_x<<<NB, 256>>>(x);
    prep_cb<<<256, 256>>>(cb);

    // smem: A 32768 + B 16384 + cvv 8192 + cix 8192 + misc 1024 = 66560 B
    size_t smem = 66560;
    cudaFuncSetAttribute(vq_main, cudaFuncAttributeMaxDynamicSharedMemorySize,
                         (int)smem);
    vq_main<<<NB, 256, smem>>>(x, cb, gcb, out_q);

    vq_finalize<<<KCODES, 256>>>(cb, gcb, snum, gnum,
                                 out_shape, out_gain, out_snum, out_gnum);
}